// round 1
// baseline (speedup 1.0000x reference)
#include <cuda_runtime.h>
#include <cstdint>

// Problem constants
#define BB    4
#define SQL   2048
#define HH    8
#define DK    64
#define DV    128
#define DKH   512     // HH*DK
#define DM    1024    // d_model
#define MROWS 8192    // BB*SQL

// Scratch (static device globals — no allocation at runtime)
__device__ float g_Q[(size_t)MROWS * DKH];   // 16 MB
__device__ float g_K[(size_t)MROWS * DKH];   // 16 MB
__device__ float g_V[(size_t)MROWS * DM];    // 32 MB
__device__ float g_O[(size_t)MROWS * DM];    // 32 MB

// ---------------------------------------------------------------------------
// Classic fp32 SGEMM: C[M,N] = A[M,K] @ B[K,N], row-major, 128x128x8 tiles,
// 256 threads, 8x8 per-thread micro-tile. M%128==0, N%128==0, K%8==0 assumed.
// ---------------------------------------------------------------------------
__global__ __launch_bounds__(256) void sgemm128(
    const float* __restrict__ A, const float* __restrict__ B,
    float* __restrict__ C, int M, int N, int K)
{
    __shared__ float As[8][128];
    __shared__ float Bs[8][128];

    const int tid = threadIdx.x;
    const int bm  = blockIdx.y;
    const int bn  = blockIdx.x;

    const int tr = tid >> 4;         // 0..15, row group
    const int tc = tid & 15;         // 0..15, col group

    const int arow = tid >> 1;             // 0..127
    const int acol = (tid & 1) << 2;       // 0 or 4
    const int brow = tid >> 5;             // 0..7
    const int bcol = (tid & 31) << 2;      // 0..124

    const float* Ab = A + (size_t)bm * 128 * K;
    const float* Bb = B + (size_t)bn * 128;

    float acc[8][8];
    #pragma unroll
    for (int i = 0; i < 8; ++i)
        #pragma unroll
        for (int j = 0; j < 8; ++j) acc[i][j] = 0.f;

    for (int kt = 0; kt < K; kt += 8) {
        float4 av = *(const float4*)(Ab + (size_t)arow * K + kt + acol);
        As[acol + 0][arow] = av.x;
        As[acol + 1][arow] = av.y;
        As[acol + 2][arow] = av.z;
        As[acol + 3][arow] = av.w;
        float4 bv = *(const float4*)(Bb + (size_t)(kt + brow) * N + bcol);
        *(float4*)(&Bs[brow][bcol]) = bv;
        __syncthreads();

        #pragma unroll
        for (int k = 0; k < 8; ++k) {
            float a[8], b[8];
            *(float4*)(a)     = *(const float4*)(&As[k][tr * 8]);
            *(float4*)(a + 4) = *(const float4*)(&As[k][tr * 8 + 4]);
            *(float4*)(b)     = *(const float4*)(&Bs[k][tc * 8]);
            *(float4*)(b + 4) = *(const float4*)(&Bs[k][tc * 8 + 4]);
            #pragma unroll
            for (int i = 0; i < 8; ++i)
                #pragma unroll
                for (int j = 0; j < 8; ++j)
                    acc[i][j] += a[i] * b[j];
        }
        __syncthreads();
    }

    float* Cb = C + (size_t)(bm * 128 + tr * 8) * N + bn * 128 + tc * 8;
    #pragma unroll
    for (int i = 0; i < 8; ++i) {
        float4 w0 = {acc[i][0], acc[i][1], acc[i][2], acc[i][3]};
        float4 w1 = {acc[i][4], acc[i][5], acc[i][6], acc[i][7]};
        *(float4*)(Cb + (size_t)i * N)     = w0;
        *(float4*)(Cb + (size_t)i * N + 4) = w1;
    }
}

// ---------------------------------------------------------------------------
// Flash-attention fp32. One block = one (b, h, 64-row Q tile).
// Online softmax over SKV in 64-row KV tiles. 256 threads = 16x16 grid:
// thread (ty,tx) owns S rows ty*4..+3, S cols tx*4..+3, O cols tx*8..+7.
// Shared: QsT[64k][68], KsT[64k][68] (k-major, padded), Vs[64][128], Ps[64][64].
// ---------------------------------------------------------------------------
__global__ __launch_bounds__(256) void flash64(
    const float* __restrict__ Q, const float* __restrict__ K,
    const float* __restrict__ V, float* __restrict__ O)
{
    extern __shared__ float sm[];
    float* QsT = sm;                        // 64*68
    float* KsT = sm + 64 * 68;              // 64*68
    float* Vs  = sm + 2 * 64 * 68;          // 64*128
    float* Ps  = Vs + 64 * 128;             // 64*64

    const int qt = blockIdx.x;
    const int h  = blockIdx.y;
    const int b  = blockIdx.z;
    const int tid = threadIdx.x;
    const int ty = tid >> 4;
    const int tx = tid & 15;

    // Load Q tile, transposed to k-major
    const float* Qg = Q + ((size_t)(b * SQL + qt * 64)) * DKH + h * DK;
    for (int idx = tid; idx < 1024; idx += 256) {
        int r  = idx >> 4;
        int k4 = (idx & 15) << 2;
        float4 v = *(const float4*)(Qg + (size_t)r * DKH + k4);
        QsT[(k4 + 0) * 68 + r] = v.x;
        QsT[(k4 + 1) * 68 + r] = v.y;
        QsT[(k4 + 2) * 68 + r] = v.z;
        QsT[(k4 + 3) * 68 + r] = v.w;
    }

    float m[4], l[4], o[4][8];
    #pragma unroll
    for (int i = 0; i < 4; ++i) {
        m[i] = -1e30f; l[i] = 0.f;
        #pragma unroll
        for (int j = 0; j < 8; ++j) o[i][j] = 0.f;
    }

    for (int jt = 0; jt < SQL / 64; ++jt) {
        __syncthreads();   // protect KsT/Vs/Ps from previous iteration readers

        const float* Kg = K + ((size_t)(b * SQL + jt * 64)) * DKH + h * DK;
        for (int idx = tid; idx < 1024; idx += 256) {
            int r  = idx >> 4;
            int k4 = (idx & 15) << 2;
            float4 v = *(const float4*)(Kg + (size_t)r * DKH + k4);
            KsT[(k4 + 0) * 68 + r] = v.x;
            KsT[(k4 + 1) * 68 + r] = v.y;
            KsT[(k4 + 2) * 68 + r] = v.z;
            KsT[(k4 + 3) * 68 + r] = v.w;
        }
        const float* Vg = V + ((size_t)(b * SQL + jt * 64)) * DM + h * DV;
        for (int idx = tid; idx < 2048; idx += 256) {
            int r  = idx >> 5;
            int c4 = (idx & 31) << 2;
            *(float4*)(Vs + r * 128 + c4) =
                *(const float4*)(Vg + (size_t)r * DM + c4);
        }
        __syncthreads();

        // S = Q Kt (4x4 per thread)
        float s[4][4];
        #pragma unroll
        for (int i = 0; i < 4; ++i)
            #pragma unroll
            for (int j = 0; j < 4; ++j) s[i][j] = 0.f;

        #pragma unroll 4
        for (int k = 0; k < 64; ++k) {
            float4 qv = *(const float4*)(QsT + k * 68 + ty * 4);
            float4 kv = *(const float4*)(KsT + k * 68 + tx * 4);
            s[0][0] += qv.x * kv.x; s[0][1] += qv.x * kv.y;
            s[0][2] += qv.x * kv.z; s[0][3] += qv.x * kv.w;
            s[1][0] += qv.y * kv.x; s[1][1] += qv.y * kv.y;
            s[1][2] += qv.y * kv.z; s[1][3] += qv.y * kv.w;
            s[2][0] += qv.z * kv.x; s[2][1] += qv.z * kv.y;
            s[2][2] += qv.z * kv.z; s[2][3] += qv.z * kv.w;
            s[3][0] += qv.w * kv.x; s[3][1] += qv.w * kv.y;
            s[3][2] += qv.w * kv.z; s[3][3] += qv.w * kv.w;
        }

        const float sc = 0.125f;   // 1/sqrt(64)
        #pragma unroll
        for (int i = 0; i < 4; ++i) {
            float t = fmaxf(fmaxf(s[i][0], s[i][1]), fmaxf(s[i][2], s[i][3])) * sc;
            #pragma unroll
            for (int d = 1; d < 16; d <<= 1)
                t = fmaxf(t, __shfl_xor_sync(0xffffffffu, t, d));
            float mn = fmaxf(m[i], t);
            float al = __expf(m[i] - mn);
            m[i] = mn;
            float rs = 0.f;
            #pragma unroll
            for (int j = 0; j < 4; ++j) {
                s[i][j] = __expf(s[i][j] * sc - mn);
                rs += s[i][j];
            }
            #pragma unroll
            for (int d = 1; d < 16; d <<= 1)
                rs += __shfl_xor_sync(0xffffffffu, rs, d);
            l[i] = l[i] * al + rs;
            #pragma unroll
            for (int j = 0; j < 8; ++j) o[i][j] *= al;
        }

        // P to shared
        #pragma unroll
        for (int i = 0; i < 4; ++i) {
            #pragma unroll
            for (int j = 0; j < 4; ++j)
                Ps[(ty * 4 + i) * 64 + tx * 4 + j] = s[i][j];
        }
        __syncthreads();

        // O += P @ V
        #pragma unroll 2
        for (int k = 0; k < 64; ++k) {
            float4 v0 = *(const float4*)(Vs + k * 128 + tx * 8);
            float4 v1 = *(const float4*)(Vs + k * 128 + tx * 8 + 4);
            #pragma unroll
            for (int i = 0; i < 4; ++i) {
                float p = Ps[(ty * 4 + i) * 64 + k];
                o[i][0] += p * v0.x; o[i][1] += p * v0.y;
                o[i][2] += p * v0.z; o[i][3] += p * v0.w;
                o[i][4] += p * v1.x; o[i][5] += p * v1.y;
                o[i][6] += p * v1.z; o[i][7] += p * v1.w;
            }
        }
    }

    // epilogue: normalize and store
    float* Og = O + ((size_t)(b * SQL + qt * 64)) * DM + h * DV;
    #pragma unroll
    for (int i = 0; i < 4; ++i) {
        float inv = 1.f / l[i];
        int r = ty * 4 + i;
        float4 w0 = {o[i][0] * inv, o[i][1] * inv, o[i][2] * inv, o[i][3] * inv};
        float4 w1 = {o[i][4] * inv, o[i][5] * inv, o[i][6] * inv, o[i][7] * inv};
        *(float4*)(Og + (size_t)r * DM + tx * 8)     = w0;
        *(float4*)(Og + (size_t)r * DM + tx * 8 + 4) = w1;
    }
}

// ---------------------------------------------------------------------------
// kernel_launch
// Inputs (metadata order): encoder_output, pre_output, Wq, Wk, Wv, Wo
// ---------------------------------------------------------------------------
extern "C" void kernel_launch(void* const* d_in, const int* in_sizes, int n_in,
                              void* d_out, int out_size)
{
    const float* enc = (const float*)d_in[0];
    const float* pre = (const float*)d_in[1];
    const float* Wq  = (const float*)d_in[2];
    const float* Wk  = (const float*)d_in[3];
    const float* Wv  = (const float*)d_in[4];
    const float* Wo  = (const float*)d_in[5];
    float* out = (float*)d_out;

    float *Qb, *Kb, *Vb, *Ob;
    cudaGetSymbolAddress((void**)&Qb, g_Q);
    cudaGetSymbolAddress((void**)&Kb, g_K);
    cudaGetSymbolAddress((void**)&Vb, g_V);
    cudaGetSymbolAddress((void**)&Ob, g_O);

    // Projections
    sgemm128<<<dim3(DKH / 128, MROWS / 128), 256>>>(pre, Wq, Qb, MROWS, DKH, DM);
    sgemm128<<<dim3(DKH / 128, MROWS / 128), 256>>>(enc, Wk, Kb, MROWS, DKH, DM);
    sgemm128<<<dim3(DM  / 128, MROWS / 128), 256>>>(enc, Wv, Vb, MROWS, DM,  DM);

    // Attention
    size_t smem = (size_t)(2 * 64 * 68 + 64 * 128 + 64 * 64) * sizeof(float); // 83968
    cudaFuncSetAttribute(flash64, cudaFuncAttributeMaxDynamicSharedMemorySize,
                         (int)smem);
    flash64<<<dim3(SQL / 64, HH, BB), 256, smem>>>(Qb, Kb, Vb, Ob);

    // Output projection
    sgemm128<<<dim3(DM / 128, MROWS / 128), 256>>>(Ob, Wo, out, MROWS, DM, DM);
}

// round 3
// speedup vs baseline: 3.2685x; 3.2685x over previous
#include <cuda_runtime.h>
#include <cuda_bf16.h>
#include <cstdint>

// Problem constants
#define BB    4
#define SQL   2048
#define HH    8
#define DK    64
#define DV    128
#define DKH   512     // HH*DK
#define DM    1024    // d_model
#define MROWS 8192    // BB*SQL

typedef __nv_bfloat16 bf16;

// ---------------------------------------------------------------------------
// Scratch (static device globals — no runtime allocation)
// ---------------------------------------------------------------------------
__device__ bf16 g_Qh[(size_t)MROWS * DKH];
__device__ bf16 g_Ql[(size_t)MROWS * DKH];
__device__ bf16 g_Kh[(size_t)MROWS * DKH];
__device__ bf16 g_Kl[(size_t)MROWS * DKH];
__device__ bf16 g_Vh[(size_t)MROWS * DM];
__device__ bf16 g_Vl[(size_t)MROWS * DM];
__device__ bf16 g_Ohh[(size_t)MROWS * DM];
__device__ bf16 g_Oll[(size_t)MROWS * DM];

__device__ bf16 g_preh[(size_t)MROWS * DM];
__device__ bf16 g_prel[(size_t)MROWS * DM];
__device__ bf16 g_ench[(size_t)MROWS * DM];
__device__ bf16 g_encl[(size_t)MROWS * DM];

__device__ bf16 g_WqTh[(size_t)DKH * DM];
__device__ bf16 g_WqTl[(size_t)DKH * DM];
__device__ bf16 g_WkTh[(size_t)DKH * DM];
__device__ bf16 g_WkTl[(size_t)DKH * DM];
__device__ bf16 g_WvTh[(size_t)DM * DM];
__device__ bf16 g_WvTl[(size_t)DM * DM];
__device__ bf16 g_WoTh[(size_t)DM * DM];
__device__ bf16 g_WoTl[(size_t)DM * DM];

// ---------------------------------------------------------------------------
// Helpers
// ---------------------------------------------------------------------------
__device__ __forceinline__ uint32_t smem_u32(const void* p) {
    uint32_t a;
    asm("{ .reg .u64 t; cvta.to.shared.u64 t, %1; cvt.u32.u64 %0, t; }"
        : "=r"(a) : "l"(p));
    return a;
}

// mma.sync m16n8k16 row.col bf16 -> fp32 accumulate (base ISA, sm_80+)
__device__ __forceinline__ void mma16816(float* d, const uint32_t* a,
                                         const uint32_t* b) {
    asm volatile(
        "mma.sync.aligned.m16n8k16.row.col.f32.bf16.bf16.f32 "
        "{%0,%1,%2,%3}, {%4,%5,%6,%7}, {%8,%9}, {%0,%1,%2,%3};"
        : "+f"(d[0]), "+f"(d[1]), "+f"(d[2]), "+f"(d[3])
        : "r"(a[0]), "r"(a[1]), "r"(a[2]), "r"(a[3]), "r"(b[0]), "r"(b[1]));
}

__device__ __forceinline__ void ldsm4(uint32_t* r, uint32_t a) {
    asm volatile("ldmatrix.sync.aligned.m8n8.x4.shared.b16 {%0,%1,%2,%3}, [%4];"
                 : "=r"(r[0]), "=r"(r[1]), "=r"(r[2]), "=r"(r[3]) : "r"(a));
}
__device__ __forceinline__ void ldsm4t(uint32_t* r, uint32_t a) {
    asm volatile("ldmatrix.sync.aligned.m8n8.x4.trans.shared.b16 {%0,%1,%2,%3}, [%4];"
                 : "=r"(r[0]), "=r"(r[1]), "=r"(r[2]), "=r"(r[3]) : "r"(a));
}

__device__ __forceinline__ void split_pack(float x, float y,
                                           uint32_t& h, uint32_t& l) {
    bf16 hx = __float2bfloat16_rn(x);
    bf16 hy = __float2bfloat16_rn(y);
    bf16 lx = __float2bfloat16_rn(x - __bfloat162float(hx));
    bf16 ly = __float2bfloat16_rn(y - __bfloat162float(hy));
    __nv_bfloat162 hh; hh.x = hx; hh.y = hy;
    __nv_bfloat162 ll; ll.x = lx; ll.y = ly;
    h = *reinterpret_cast<uint32_t*>(&hh);
    l = *reinterpret_cast<uint32_t*>(&ll);
}

// ---------------------------------------------------------------------------
// Conversion kernels: fp32 -> bf16 hi/lo split
// ---------------------------------------------------------------------------
__device__ __forceinline__ unsigned short bf_us(bf16 b) {
    return *reinterpret_cast<unsigned short*>(&b);
}
__device__ __forceinline__ void split1(float x, unsigned short& h, unsigned short& l) {
    bf16 hv = __float2bfloat16_rn(x);
    float r = x - __bfloat162float(hv);
    bf16 lv = __float2bfloat16_rn(r);
    h = bf_us(hv); l = bf_us(lv);
}

__global__ __launch_bounds__(256) void cvt_hilo(
    const float4* __restrict__ in, ushort4* __restrict__ hi,
    ushort4* __restrict__ lo, int n4)
{
    int i = blockIdx.x * 256 + threadIdx.x;
    if (i >= n4) return;
    float4 v = in[i];
    ushort4 h, l;
    split1(v.x, h.x, l.x);
    split1(v.y, h.y, l.y);
    split1(v.z, h.z, l.z);
    split1(v.w, h.w, l.w);
    hi[i] = h; lo[i] = l;
}

// transpose + split: in [R,C] fp32 -> out [C,R] bf16 hi/lo
__global__ void cvtT_hilo(const float* __restrict__ in,
                          bf16* __restrict__ hiT, bf16* __restrict__ loT,
                          int R, int C)
{
    __shared__ float t[32][33];
    int c0 = blockIdx.x * 32, r0 = blockIdx.y * 32;
    int tx = threadIdx.x, ty = threadIdx.y;
    #pragma unroll
    for (int i = 0; i < 32; i += 8)
        t[ty + i][tx] = in[(size_t)(r0 + ty + i) * C + c0 + tx];
    __syncthreads();
    #pragma unroll
    for (int i = 0; i < 32; i += 8) {
        float x = t[tx][ty + i];
        unsigned short h, l;
        split1(x, h, l);
        size_t o = (size_t)(c0 + ty + i) * R + r0 + tx;
        reinterpret_cast<unsigned short*>(hiT)[o] = h;
        reinterpret_cast<unsigned short*>(loT)[o] = l;
    }
}

// ---------------------------------------------------------------------------
// HMMA GEMM: C[M,N] = (Ah+Al)[M,K] @ (Bh+Bl)[N,K]^T  (bf16 3x split)
// CTA 128x128, k-step 32, 8 warps (4M x 2N), double-buffered smem.
// MODE 0: write fp32 C.  MODE 1: write bf16 hi/lo split (Ch, Cl).
// ---------------------------------------------------------------------------
#define G_STG 40960u
#define G_OAH 0u
#define G_OAL 10240u
#define G_OBH 20480u
#define G_OBL 30720u
#define G_SMEM (2u * G_STG)   // 81920

template<int MODE>
__global__ __launch_bounds__(256) void hgemm(
    const bf16* __restrict__ Ahp, const bf16* __restrict__ Alp,
    const bf16* __restrict__ Bhp, const bf16* __restrict__ Blp,
    float* __restrict__ C, bf16* __restrict__ Ch, bf16* __restrict__ Cl,
    int M, int N, int K)
{
    extern __shared__ char smc[];
    const uint32_t sb = smem_u32(smc);
    const int tid = threadIdx.x;
    const int lane = tid & 31, wid = tid >> 5;
    const int wm = wid >> 1, wn = wid & 1;
    const int bm = blockIdx.y, bn = blockIdx.x;
    const int l7 = lane & 7, lb3 = (lane >> 3) & 1, lb4 = (lane >> 4) & 1;
    const int g = lane >> 2, t4 = lane & 3;

    // ldg/sts indexing: 2 slots per array
    const int r0 = tid >> 2,        c0 = tid & 3;
    const int r1 = (tid + 256) >> 2, c1 = (tid + 256) & 3;

    const bf16* Ag  = Ahp + (size_t)(bm * 128) * K;
    const bf16* Ag2 = Alp + (size_t)(bm * 128) * K;
    const bf16* Bg  = Bhp + (size_t)(bn * 128) * K;
    const bf16* Bg2 = Blp + (size_t)(bn * 128) * K;

    float acc[2][8][4];
    #pragma unroll
    for (int mi = 0; mi < 2; ++mi)
        #pragma unroll
        for (int nt = 0; nt < 8; ++nt)
            #pragma unroll
            for (int j = 0; j < 4; ++j) acc[mi][nt][j] = 0.f;

    uint4 rg[8];
    auto ldg = [&](int kc) {
        size_t o0 = (size_t)r0 * K + kc * 32 + c0 * 8;
        size_t o1 = (size_t)r1 * K + kc * 32 + c1 * 8;
        rg[0] = *(const uint4*)(Ag  + o0); rg[1] = *(const uint4*)(Ag  + o1);
        rg[2] = *(const uint4*)(Ag2 + o0); rg[3] = *(const uint4*)(Ag2 + o1);
        rg[4] = *(const uint4*)(Bg  + o0); rg[5] = *(const uint4*)(Bg  + o1);
        rg[6] = *(const uint4*)(Bg2 + o0); rg[7] = *(const uint4*)(Bg2 + o1);
    };
    auto sts = [&](int s) {
        char* base = smc + (uint32_t)s * G_STG;
        uint32_t d0 = (uint32_t)(r0 * 40 + c0 * 8) * 2;
        uint32_t d1 = (uint32_t)(r1 * 40 + c1 * 8) * 2;
        *(uint4*)(base + G_OAH + d0) = rg[0]; *(uint4*)(base + G_OAH + d1) = rg[1];
        *(uint4*)(base + G_OAL + d0) = rg[2]; *(uint4*)(base + G_OAL + d1) = rg[3];
        *(uint4*)(base + G_OBH + d0) = rg[4]; *(uint4*)(base + G_OBH + d1) = rg[5];
        *(uint4*)(base + G_OBL + d0) = rg[6]; *(uint4*)(base + G_OBL + d1) = rg[7];
    };

    auto compute = [&](int s) {
        uint32_t base = sb + (uint32_t)s * G_STG;
        #pragma unroll
        for (int kt = 0; kt < 2; ++kt) {
            uint32_t ah[2][4], al[2][4];
            #pragma unroll
            for (int mi = 0; mi < 2; ++mi) {
                uint32_t off = (uint32_t)((wm * 32 + mi * 16 + l7 + lb3 * 8) * 40
                                          + kt * 16 + lb4 * 8) * 2;
                ldsm4(ah[mi], base + G_OAH + off);
                ldsm4(al[mi], base + G_OAL + off);
            }
            uint32_t bh[4][4], bl[4][4];
            #pragma unroll
            for (int nb = 0; nb < 4; ++nb) {
                uint32_t off = (uint32_t)((wn * 64 + nb * 16 + l7 + lb4 * 8) * 40
                                          + kt * 16 + lb3 * 8) * 2;
                ldsm4(bh[nb], base + G_OBH + off);
                ldsm4(bl[nb], base + G_OBL + off);
            }
            #pragma unroll
            for (int mi = 0; mi < 2; ++mi)
                #pragma unroll
                for (int nb = 0; nb < 4; ++nb)
                    #pragma unroll
                    for (int hf = 0; hf < 2; ++hf) {
                        int nt = nb * 2 + hf;
                        mma16816(acc[mi][nt], ah[mi], &bh[nb][hf * 2]);
                        mma16816(acc[mi][nt], ah[mi], &bl[nb][hf * 2]);
                        mma16816(acc[mi][nt], al[mi], &bh[nb][hf * 2]);
                    }
        }
    };

    const int NS = K >> 5;
    ldg(0); sts(0);
    __syncthreads();
    for (int s = 0; s < NS; ++s) {
        if (s + 1 < NS) ldg(s + 1);
        compute(s & 1);
        if (s + 1 < NS) sts((s + 1) & 1);
        __syncthreads();
    }

    // epilogue
    #pragma unroll
    for (int mi = 0; mi < 2; ++mi) {
        #pragma unroll
        for (int nt = 0; nt < 8; ++nt) {
            int row = bm * 128 + wm * 32 + mi * 16 + g;
            int col = bn * 128 + wn * 64 + nt * 8 + t4 * 2;
            if (MODE == 0) {
                float2 w0 = {acc[mi][nt][0], acc[mi][nt][1]};
                float2 w1 = {acc[mi][nt][2], acc[mi][nt][3]};
                *(float2*)(C + (size_t)row * N + col)       = w0;
                *(float2*)(C + (size_t)(row + 8) * N + col) = w1;
            } else {
                uint32_t h0, l0, h1, l1;
                split_pack(acc[mi][nt][0], acc[mi][nt][1], h0, l0);
                split_pack(acc[mi][nt][2], acc[mi][nt][3], h1, l1);
                *(uint32_t*)(Ch + (size_t)row * N + col)       = h0;
                *(uint32_t*)(Cl + (size_t)row * N + col)       = l0;
                *(uint32_t*)(Ch + (size_t)(row + 8) * N + col) = h1;
                *(uint32_t*)(Cl + (size_t)(row + 8) * N + col) = l1;
            }
        }
    }
}

// ---------------------------------------------------------------------------
// HMMA flash attention. Block = (b, h, 128-row Q tile), 8 warps x 16 rows.
// bf16x3 split for both QK^T and PV. KV tiles of 64.
// ---------------------------------------------------------------------------
#define F_QH 0u
#define F_QL 18432u        // 128*72*2
#define F_KH 36864u
#define F_KL 46080u        // + 64*72*2
#define F_VH 55296u
#define F_VL 72704u        // + 64*136*2
#define F_SMEM 90112u

__global__ __launch_bounds__(256) void flash_hmma(
    const bf16* __restrict__ Qh, const bf16* __restrict__ Ql,
    const bf16* __restrict__ Kh, const bf16* __restrict__ Kl,
    const bf16* __restrict__ Vh, const bf16* __restrict__ Vl,
    bf16* __restrict__ Oh, bf16* __restrict__ Ol)
{
    extern __shared__ char smc[];
    const uint32_t sb = smem_u32(smc);
    const int qt = blockIdx.x, h = blockIdx.y, b = blockIdx.z;
    const int tid = threadIdx.x;
    const int lane = tid & 31, wid = tid >> 5;
    const int l7 = lane & 7, lb3 = (lane >> 3) & 1, lb4 = (lane >> 4) & 1;
    const int g = lane >> 2, t4 = lane & 3;

    // load Q tile (hi, lo): [128][64] -> smem stride 72
    {
        const bf16* Qgh = Qh + ((size_t)(b * SQL + qt * 128)) * DKH + h * DK;
        const bf16* Qgl = Ql + ((size_t)(b * SQL + qt * 128)) * DKH + h * DK;
        #pragma unroll
        for (int i = tid; i < 1024; i += 256) {
            int r = i >> 3, c = i & 7;
            uint32_t d = (uint32_t)(r * 72 + c * 8) * 2;
            *(uint4*)(smc + F_QH + d) = *(const uint4*)(Qgh + (size_t)r * DKH + c * 8);
            *(uint4*)(smc + F_QL + d) = *(const uint4*)(Qgl + (size_t)r * DKH + c * 8);
        }
    }

    float o[16][4];
    #pragma unroll
    for (int nt = 0; nt < 16; ++nt)
        #pragma unroll
        for (int j = 0; j < 4; ++j) o[nt][j] = 0.f;
    float m0 = -1e30f, m1 = -1e30f, l0 = 0.f, l1 = 0.f;
    const float SC = 0.125f;

    for (int jt = 0; jt < SQL / 64; ++jt) {
        __syncthreads();
        // load K tile [64][64], V tile [64][128] (hi+lo)
        {
            const bf16* Kgh = Kh + ((size_t)(b * SQL + jt * 64)) * DKH + h * DK;
            const bf16* Kgl = Kl + ((size_t)(b * SQL + jt * 64)) * DKH + h * DK;
            #pragma unroll
            for (int i = tid; i < 512; i += 256) {
                int r = i >> 3, c = i & 7;
                uint32_t d = (uint32_t)(r * 72 + c * 8) * 2;
                *(uint4*)(smc + F_KH + d) = *(const uint4*)(Kgh + (size_t)r * DKH + c * 8);
                *(uint4*)(smc + F_KL + d) = *(const uint4*)(Kgl + (size_t)r * DKH + c * 8);
            }
            const bf16* Vgh = Vh + ((size_t)(b * SQL + jt * 64)) * DM + h * DV;
            const bf16* Vgl = Vl + ((size_t)(b * SQL + jt * 64)) * DM + h * DV;
            #pragma unroll
            for (int i = tid; i < 1024; i += 256) {
                int r = i >> 4, c = i & 15;
                uint32_t d = (uint32_t)(r * 136 + c * 8) * 2;
                *(uint4*)(smc + F_VH + d) = *(const uint4*)(Vgh + (size_t)r * DM + c * 8);
                *(uint4*)(smc + F_VL + d) = *(const uint4*)(Vgl + (size_t)r * DM + c * 8);
            }
        }
        __syncthreads();

        // S = Q K^T (bf16x3)
        float s[8][4];
        #pragma unroll
        for (int nt = 0; nt < 8; ++nt)
            #pragma unroll
            for (int j = 0; j < 4; ++j) s[nt][j] = 0.f;

        #pragma unroll
        for (int kt = 0; kt < 4; ++kt) {
            uint32_t qfh[4], qfl[4];
            uint32_t qoff = (uint32_t)((wid * 16 + l7 + lb3 * 8) * 72
                                       + kt * 16 + lb4 * 8) * 2;
            ldsm4(qfh, sb + F_QH + qoff);
            ldsm4(qfl, sb + F_QL + qoff);
            #pragma unroll
            for (int nb = 0; nb < 4; ++nb) {
                uint32_t kfh[4], kfl[4];
                uint32_t koff = (uint32_t)((nb * 16 + l7 + lb4 * 8) * 72
                                           + kt * 16 + lb3 * 8) * 2;
                ldsm4(kfh, sb + F_KH + koff);
                ldsm4(kfl, sb + F_KL + koff);
                #pragma unroll
                for (int hf = 0; hf < 2; ++hf) {
                    int nt = nb * 2 + hf;
                    mma16816(s[nt], qfh, &kfh[hf * 2]);
                    mma16816(s[nt], qfh, &kfl[hf * 2]);
                    mma16816(s[nt], qfl, &kfh[hf * 2]);
                }
            }
        }

        // online softmax (rows g and g+8 of this warp's 16 rows)
        float rmax0 = -1e30f, rmax1 = -1e30f;
        #pragma unroll
        for (int nt = 0; nt < 8; ++nt) {
            rmax0 = fmaxf(rmax0, fmaxf(s[nt][0], s[nt][1]));
            rmax1 = fmaxf(rmax1, fmaxf(s[nt][2], s[nt][3]));
        }
        rmax0 = fmaxf(rmax0, __shfl_xor_sync(0xffffffffu, rmax0, 1));
        rmax0 = fmaxf(rmax0, __shfl_xor_sync(0xffffffffu, rmax0, 2));
        rmax1 = fmaxf(rmax1, __shfl_xor_sync(0xffffffffu, rmax1, 1));
        rmax1 = fmaxf(rmax1, __shfl_xor_sync(0xffffffffu, rmax1, 2));
        float mn0 = fmaxf(m0, rmax0 * SC);
        float mn1 = fmaxf(m1, rmax1 * SC);
        float al0 = __expf(m0 - mn0), al1 = __expf(m1 - mn1);
        m0 = mn0; m1 = mn1;

        uint32_t pAh[2][8], pAl[2][8];
        float rs0 = 0.f, rs1 = 0.f;
        #pragma unroll
        for (int nt = 0; nt < 8; ++nt) {
            float p0 = __expf(s[nt][0] * SC - m0);
            float p1 = __expf(s[nt][1] * SC - m0);
            float p2 = __expf(s[nt][2] * SC - m1);
            float p3 = __expf(s[nt][3] * SC - m1);
            rs0 += p0 + p1; rs1 += p2 + p3;
            split_pack(p0, p1, pAh[0][nt], pAl[0][nt]);
            split_pack(p2, p3, pAh[1][nt], pAl[1][nt]);
        }
        rs0 += __shfl_xor_sync(0xffffffffu, rs0, 1);
        rs0 += __shfl_xor_sync(0xffffffffu, rs0, 2);
        rs1 += __shfl_xor_sync(0xffffffffu, rs1, 1);
        rs1 += __shfl_xor_sync(0xffffffffu, rs1, 2);
        l0 = l0 * al0 + rs0;
        l1 = l1 * al1 + rs1;
        #pragma unroll
        for (int nt = 0; nt < 16; ++nt) {
            o[nt][0] *= al0; o[nt][1] *= al0;
            o[nt][2] *= al1; o[nt][3] *= al1;
        }

        // O += P V (bf16x3), V via ldmatrix.trans
        #pragma unroll
        for (int kt = 0; kt < 4; ++kt) {
            uint32_t pfh[4] = {pAh[0][2 * kt], pAh[1][2 * kt],
                               pAh[0][2 * kt + 1], pAh[1][2 * kt + 1]};
            uint32_t pfl[4] = {pAl[0][2 * kt], pAl[1][2 * kt],
                               pAl[0][2 * kt + 1], pAl[1][2 * kt + 1]};
            #pragma unroll
            for (int np = 0; np < 8; ++np) {
                uint32_t vfh[4], vfl[4];
                uint32_t voff = (uint32_t)((kt * 16 + l7 + lb3 * 8) * 136
                                           + np * 16 + lb4 * 8) * 2;
                ldsm4t(vfh, sb + F_VH + voff);
                ldsm4t(vfl, sb + F_VL + voff);
                #pragma unroll
                for (int hf = 0; hf < 2; ++hf) {
                    int nt = np * 2 + hf;
                    mma16816(o[nt], pfh, &vfh[hf * 2]);
                    mma16816(o[nt], pfh, &vfl[hf * 2]);
                    mma16816(o[nt], pfl, &vfh[hf * 2]);
                }
            }
        }
    }

    // epilogue: normalize, split, write bf16 hi/lo
    float i0 = 1.f / l0, i1 = 1.f / l1;
    int row = b * SQL + qt * 128 + wid * 16 + g;
    #pragma unroll
    for (int nt = 0; nt < 16; ++nt) {
        int col = h * DV + nt * 8 + t4 * 2;
        uint32_t h0, lo0, h1, lo1;
        split_pack(o[nt][0] * i0, o[nt][1] * i0, h0, lo0);
        split_pack(o[nt][2] * i1, o[nt][3] * i1, h1, lo1);
        *(uint32_t*)(Oh + (size_t)row * DM + col)       = h0;
        *(uint32_t*)(Ol + (size_t)row * DM + col)       = lo0;
        *(uint32_t*)(Oh + (size_t)(row + 8) * DM + col) = h1;
        *(uint32_t*)(Ol + (size_t)(row + 8) * DM + col) = lo1;
    }
}

// ---------------------------------------------------------------------------
// kernel_launch — inputs: encoder_output, pre_output, Wq, Wk, Wv, Wo
// ---------------------------------------------------------------------------
extern "C" void kernel_launch(void* const* d_in, const int* in_sizes, int n_in,
                              void* d_out, int out_size)
{
    const float* enc = (const float*)d_in[0];
    const float* pre = (const float*)d_in[1];
    const float* Wq  = (const float*)d_in[2];
    const float* Wk  = (const float*)d_in[3];
    const float* Wv  = (const float*)d_in[4];
    const float* Wo  = (const float*)d_in[5];
    float* out = (float*)d_out;

    bf16 *Qh, *Ql, *Kh, *Kl, *Vh, *Vl, *Ohh, *Oll;
    bf16 *preh, *prel, *ench, *encl;
    bf16 *WqTh, *WqTl, *WkTh, *WkTl, *WvTh, *WvTl, *WoTh, *WoTl;
    cudaGetSymbolAddress((void**)&Qh, g_Qh);   cudaGetSymbolAddress((void**)&Ql, g_Ql);
    cudaGetSymbolAddress((void**)&Kh, g_Kh);   cudaGetSymbolAddress((void**)&Kl, g_Kl);
    cudaGetSymbolAddress((void**)&Vh, g_Vh);   cudaGetSymbolAddress((void**)&Vl, g_Vl);
    cudaGetSymbolAddress((void**)&Ohh, g_Ohh); cudaGetSymbolAddress((void**)&Oll, g_Oll);
    cudaGetSymbolAddress((void**)&preh, g_preh); cudaGetSymbolAddress((void**)&prel, g_prel);
    cudaGetSymbolAddress((void**)&ench, g_ench); cudaGetSymbolAddress((void**)&encl, g_encl);
    cudaGetSymbolAddress((void**)&WqTh, g_WqTh); cudaGetSymbolAddress((void**)&WqTl, g_WqTl);
    cudaGetSymbolAddress((void**)&WkTh, g_WkTh); cudaGetSymbolAddress((void**)&WkTl, g_WkTl);
    cudaGetSymbolAddress((void**)&WvTh, g_WvTh); cudaGetSymbolAddress((void**)&WvTl, g_WvTl);
    cudaGetSymbolAddress((void**)&WoTh, g_WoTh); cudaGetSymbolAddress((void**)&WoTl, g_WoTl);

    cudaFuncSetAttribute(hgemm<0>, cudaFuncAttributeMaxDynamicSharedMemorySize, G_SMEM);
    cudaFuncSetAttribute(hgemm<1>, cudaFuncAttributeMaxDynamicSharedMemorySize, G_SMEM);
    cudaFuncSetAttribute(flash_hmma, cudaFuncAttributeMaxDynamicSharedMemorySize, F_SMEM);

    // activations -> bf16 hi/lo
    const int nAct4 = MROWS * DM / 4;
    cvt_hilo<<<(nAct4 + 255) / 256, 256>>>((const float4*)pre,
                                           (ushort4*)preh, (ushort4*)prel, nAct4);
    cvt_hilo<<<(nAct4 + 255) / 256, 256>>>((const float4*)enc,
                                           (ushort4*)ench, (ushort4*)encl, nAct4);

    // weights -> transposed bf16 hi/lo ([K,N] fp32 -> [N,K] bf16)
    cvtT_hilo<<<dim3(DKH / 32, DM / 32), dim3(32, 8)>>>(Wq, WqTh, WqTl, DM, DKH);
    cvtT_hilo<<<dim3(DKH / 32, DM / 32), dim3(32, 8)>>>(Wk, WkTh, WkTl, DM, DKH);
    cvtT_hilo<<<dim3(DM  / 32, DM / 32), dim3(32, 8)>>>(Wv, WvTh, WvTl, DM, DM);
    cvtT_hilo<<<dim3(DM  / 32, DM / 32), dim3(32, 8)>>>(Wo, WoTh, WoTl, DM, DM);

    // projections (write bf16 hi/lo directly)
    hgemm<1><<<dim3(DKH / 128, MROWS / 128), 256, G_SMEM>>>(
        preh, prel, WqTh, WqTl, nullptr, Qh, Ql, MROWS, DKH, DM);
    hgemm<1><<<dim3(DKH / 128, MROWS / 128), 256, G_SMEM>>>(
        ench, encl, WkTh, WkTl, nullptr, Kh, Kl, MROWS, DKH, DM);
    hgemm<1><<<dim3(DM / 128, MROWS / 128), 256, G_SMEM>>>(
        ench, encl, WvTh, WvTl, nullptr, Vh, Vl, MROWS, DM, DM);

    // attention
    flash_hmma<<<dim3(SQL / 128, HH, BB), 256, F_SMEM>>>(
        Qh, Ql, Kh, Kl, Vh, Vl, Ohh, Oll);

    // output projection (fp32 out)
    hgemm<0><<<dim3(DM / 128, MROWS / 128), 256, G_SMEM>>>(
        Ohh, Oll, WoTh, WoTl, out, nullptr, nullptr, MROWS, DM, DM);
}